// round 2
// baseline (speedup 1.0000x reference)
#include <cuda_runtime.h>
#include <math.h>

#define D1V 270
#define KV 32
#define CV 60
#define BV 64
#define TV 4096
#define KL (KV*KV)          // 1024
#define JPAD 288            // 270 padded to multiple of 32
#define TTILE 128

// Scratch (device globals: no allocation allowed)
__device__ __align__(16) float g_cs[KL*CV];
__device__ __align__(16) float g_sn[KL*CV];
__device__ __align__(16) float g_wT[CV*JPAD];   // transposed weights wT[c][j], zero-padded j>=270

// ---------------------------------------------------------------------------
// Kernel A: trig tables  cs[(k*32+l)*60 + c] = cos(2pi*(k*x[c]+l*y[c]))
// ---------------------------------------------------------------------------
__global__ void phase_kernel(const float* __restrict__ loc) {
    int idx = blockIdx.x * blockDim.x + threadIdx.x;
    if (idx >= KL * CV) return;
    int c  = idx % CV;
    int kl = idx / CV;
    int k = kl >> 5, l = kl & 31;
    float x = loc[c * 2 + 0];
    float y = loc[c * 2 + 1];
    float ph = 6.283185307179586f * ((float)k * x + (float)l * y);
    float s, co;
    sincosf(ph, &s, &co);
    g_cs[idx] = co;
    g_sn[idx] = s;
}

// ---------------------------------------------------------------------------
// Kernel B: a[j,c] = sum_kl z_re*cs + z_im*sn ; softmax over c ; write wT
// One block per j (288 blocks; j>=270 writes zero pad). 64 threads, c = tid.
// ---------------------------------------------------------------------------
__global__ void weight_kernel(const float* __restrict__ z_re,
                              const float* __restrict__ z_im) {
    int j = blockIdx.x;
    int c = threadIdx.x;
    __shared__ float red[64];

    if (j >= D1V) {
        if (c < CV) g_wT[c * JPAD + j] = 0.f;
        return;
    }

    float acc = 0.f;
    if (c < CV) {
        const float* zr = z_re + (size_t)j * KL;
        const float* zi = z_im + (size_t)j * KL;
        #pragma unroll 8
        for (int kl = 0; kl < KL; ++kl) {
            acc = fmaf(zr[kl], g_cs[kl * CV + c], acc);
            acc = fmaf(zi[kl], g_sn[kl * CV + c], acc);
        }
    }

    // max over c (numerically safe softmax; mathematically identical to ref)
    red[c] = (c < CV) ? acc : -3.402823466e38f;
    __syncthreads();
    for (int off = 32; off > 0; off >>= 1) {
        if (c < off) red[c] = fmaxf(red[c], red[c + off]);
        __syncthreads();
    }
    float m = red[0];
    __syncthreads();

    float e = (c < CV) ? expf(acc - m) : 0.f;
    red[c] = e;
    __syncthreads();
    for (int off = 32; off > 0; off >>= 1) {
        if (c < off) red[c] += red[c + off];
        __syncthreads();
    }
    float s = red[0];

    if (c < CV) g_wT[c * JPAD + j] = e / s;
}

// ---------------------------------------------------------------------------
// Kernel C: out[b,j,t] = sum_c wT[c][j] * X[b,c,t]
// Grid: (T/TTILE, B). Block: 256 threads = 8 warps.
// Warp w handles j = jb*32 + w*4 + {0..3}; lane handles t = t0 + lane*4 + {0..3}.
// Per c-iter: 1 LDS.128 (X, conflict-free) + 1 LDG.128 (w, uniform broadcast)
// + 16 FFMA  -> FFMA-pipe bound.
// ---------------------------------------------------------------------------
__global__ void __launch_bounds__(256) out_kernel(const float* __restrict__ X,
                                                  float* __restrict__ out) {
    __shared__ __align__(16) float Xs[CV * TTILE];

    int b  = blockIdx.y;
    int t0 = blockIdx.x * TTILE;

    // Stage X[b, :, t0:t0+TTILE] into smem (vectorized, coalesced)
    const float* Xb = X + (size_t)b * CV * TV + t0;
    for (int idx = threadIdx.x; idx < CV * (TTILE / 4); idx += 256) {
        int c = idx / (TTILE / 4);
        int q = idx - c * (TTILE / 4);
        float4 v = *reinterpret_cast<const float4*>(Xb + (size_t)c * TV + q * 4);
        reinterpret_cast<float4*>(Xs)[idx] = v;
    }
    __syncthreads();

    int lane = threadIdx.x & 31;
    int wy   = threadIdx.x >> 5;
    int tl   = lane * 4;

    float* outp = out + (size_t)b * D1V * TV + t0 + tl;

    for (int jb = 0; jb < JPAD / 32; ++jb) {
        int j0 = jb * 32 + wy * 4;

        float a0x = 0.f, a0y = 0.f, a0z = 0.f, a0w = 0.f;
        float a1x = 0.f, a1y = 0.f, a1z = 0.f, a1w = 0.f;
        float a2x = 0.f, a2y = 0.f, a2z = 0.f, a2w = 0.f;
        float a3x = 0.f, a3y = 0.f, a3z = 0.f, a3w = 0.f;

        #pragma unroll
        for (int c = 0; c < CV; ++c) {
            float4 xv = *reinterpret_cast<const float4*>(&Xs[c * TTILE + tl]);
            float4 wv = *reinterpret_cast<const float4*>(&g_wT[c * JPAD + j0]);
            a0x = fmaf(wv.x, xv.x, a0x); a0y = fmaf(wv.x, xv.y, a0y);
            a0z = fmaf(wv.x, xv.z, a0z); a0w = fmaf(wv.x, xv.w, a0w);
            a1x = fmaf(wv.y, xv.x, a1x); a1y = fmaf(wv.y, xv.y, a1y);
            a1z = fmaf(wv.y, xv.z, a1z); a1w = fmaf(wv.y, xv.w, a1w);
            a2x = fmaf(wv.z, xv.x, a2x); a2y = fmaf(wv.z, xv.y, a2y);
            a2z = fmaf(wv.z, xv.z, a2z); a2w = fmaf(wv.z, xv.w, a2w);
            a3x = fmaf(wv.w, xv.x, a3x); a3y = fmaf(wv.w, xv.y, a3y);
            a3z = fmaf(wv.w, xv.z, a3z); a3w = fmaf(wv.w, xv.w, a3w);
        }

        if (j0 + 0 < D1V) {
            float4 o = make_float4(a0x, a0y, a0z, a0w);
            *reinterpret_cast<float4*>(outp + (size_t)(j0 + 0) * TV) = o;
        }
        if (j0 + 1 < D1V) {
            float4 o = make_float4(a1x, a1y, a1z, a1w);
            *reinterpret_cast<float4*>(outp + (size_t)(j0 + 1) * TV) = o;
        }
        if (j0 + 2 < D1V) {
            float4 o = make_float4(a2x, a2y, a2z, a2w);
            *reinterpret_cast<float4*>(outp + (size_t)(j0 + 2) * TV) = o;
        }
        if (j0 + 3 < D1V) {
            float4 o = make_float4(a3x, a3y, a3z, a3w);
            *reinterpret_cast<float4*>(outp + (size_t)(j0 + 3) * TV) = o;
        }
    }
}

// ---------------------------------------------------------------------------
extern "C" void kernel_launch(void* const* d_in, const int* in_sizes, int n_in,
                              void* d_out, int out_size) {
    const float* X    = (const float*)d_in[0];
    const float* z_re = (const float*)d_in[1];
    const float* z_im = (const float*)d_in[2];
    const float* loc  = (const float*)d_in[3];
    float* out = (float*)d_out;

    phase_kernel<<<(KL * CV + 255) / 256, 256>>>(loc);
    weight_kernel<<<JPAD, 64>>>(z_re, z_im);
    out_kernel<<<dim3(TV / TTILE, BV), 256>>>(X, out);
}

// round 3
// speedup vs baseline: 8.0436x; 8.0436x over previous
#include <cuda_runtime.h>
#include <math.h>

#define D1V 270
#define KV 32
#define CV 60
#define BV 64
#define TV 4096
#define KL (KV*KV)          // 1024
#define JPAD 288            // 270 padded to multiple of 32
#define TTILE 128

typedef unsigned long long ull;

// Scratch (device globals: no allocation allowed)
__device__ __align__(16) float g_cs[KL*CV];
__device__ __align__(16) float g_sn[KL*CV];
__device__ __align__(16) float g_wT[CV*JPAD];   // wT[c][j], zero-padded j>=270

// packed fp32x2 FMA (sm_10x): d = a*b + c per 32-bit lane
__device__ __forceinline__ ull ffma2(ull a, ull b, ull c) {
    ull d;
    asm("fma.rn.f32x2 %0, %1, %2, %3;" : "=l"(d) : "l"(a), "l"(b), "l"(c));
    return d;
}

// ---------------------------------------------------------------------------
// Kernel A: trig tables  cs[(k*32+l)*60 + c] = cos(2pi*(k*x[c]+l*y[c]))
// ---------------------------------------------------------------------------
__global__ void phase_kernel(const float* __restrict__ loc) {
    int idx = blockIdx.x * blockDim.x + threadIdx.x;
    if (idx >= KL * CV) return;
    int c  = idx % CV;
    int kl = idx / CV;
    int k = kl >> 5, l = kl & 31;
    float x = loc[c * 2 + 0];
    float y = loc[c * 2 + 1];
    float ph = 6.283185307179586f * ((float)k * x + (float)l * y);
    float s, co;
    sincosf(ph, &s, &co);
    g_cs[idx] = co;
    g_sn[idx] = s;
}

// ---------------------------------------------------------------------------
// Kernel B: a[j,c] = sum_kl z_re*cs + z_im*sn ; softmax over c ; write wT
// 256 threads: c = tid&63 (c<60 active), kl-range split across 4 groups
// (tid>>6) to break the serial dependence chain 4x.
// ---------------------------------------------------------------------------
__global__ void __launch_bounds__(256) weight_kernel(const float* __restrict__ z_re,
                                                     const float* __restrict__ z_im) {
    int j   = blockIdx.x;
    int tid = threadIdx.x;
    int c   = tid & 63;
    int g   = tid >> 6;      // 0..3
    __shared__ float part[256];
    __shared__ float red[64];

    if (j >= D1V) {
        if (tid < CV) g_wT[tid * JPAD + j] = 0.f;
        return;
    }

    float acc = 0.f;
    if (c < CV) {
        const float* zr = z_re + (size_t)j * KL;
        const float* zi = z_im + (size_t)j * KL;
        int kl0 = g * (KL / 4);
        #pragma unroll 8
        for (int kl = kl0; kl < kl0 + KL / 4; ++kl) {
            acc = fmaf(zr[kl], g_cs[kl * CV + c], acc);
            acc = fmaf(zi[kl], g_sn[kl * CV + c], acc);
        }
    }
    part[tid] = acc;
    __syncthreads();

    float tot = 0.f;
    if (tid < 64)
        tot = part[tid] + part[tid + 64] + part[tid + 128] + part[tid + 192];

    // max over c (safe softmax)
    if (tid < 64) red[tid] = (tid < CV) ? tot : -3.402823466e38f;
    __syncthreads();
    for (int off = 32; off > 0; off >>= 1) {
        if (tid < off) red[tid] = fmaxf(red[tid], red[tid + off]);
        __syncthreads();
    }
    float m = red[0];
    __syncthreads();

    float e = (tid < CV) ? expf(tot - m) : 0.f;
    if (tid < 64) red[tid] = e;
    __syncthreads();
    for (int off = 32; off > 0; off >>= 1) {
        if (tid < off) red[tid] += red[tid + off];
        __syncthreads();
    }
    float s = red[0];

    if (tid < CV) g_wT[tid * JPAD + j] = e / s;
}

// ---------------------------------------------------------------------------
// Kernel C: out[b,j,t] = sum_c wT[c][j] * X[b,c,t]
// Grid: (T/128, B). 256 threads = 8 warps. Warp wy -> 4 j's; lane -> 4 t's.
// W slice for the current 32-j block is staged in smem PRE-DUPLICATED
// ({w,w} pairs) so it loads directly as a packed f32x2 operand.
// Inner c-iter: 3x LDS.128 + 8x FFMA2  -> packed-FMA-pipe bound, no LDG,
// bounded unroll -> no spills.
// ---------------------------------------------------------------------------
__global__ void __launch_bounds__(256) out_kernel(const float* __restrict__ X,
                                                  float* __restrict__ out) {
    __shared__ __align__(16) float Xs[CV * TTILE];   // 30 KB
    __shared__ __align__(16) float Ws2[CV * 64];     // 15 KB: [c][jj*2+{0,1}] dup

    int b  = blockIdx.y;
    int t0 = blockIdx.x * TTILE;
    int tid = threadIdx.x;

    // Stage X[b, :, t0:t0+128] (vectorized, coalesced)
    const float* Xb = X + (size_t)b * CV * TV + t0;
    for (int idx = tid; idx < CV * (TTILE / 4); idx += 256) {
        int c = idx / (TTILE / 4);
        int q = idx - c * (TTILE / 4);
        reinterpret_cast<float4*>(Xs)[idx] =
            *reinterpret_cast<const float4*>(Xb + (size_t)c * TV + q * 4);
    }

    int lane = tid & 31;
    int wy   = tid >> 5;
    int tl   = lane * 4;
    float* outp = out + (size_t)b * D1V * TV + t0 + tl;

    for (int jb = 0; jb < JPAD / 32; ++jb) {
        __syncthreads();   // previous tile's reads done before Ws2 overwrite
        // Stage W slice duplicated: Ws2[c*64 + jj*2 + {0,1}] = wT[c][jb*32+jj]
        for (int idx = tid; idx < CV * 32; idx += 256) {
            int c  = idx >> 5;
            int jj = idx & 31;
            float w = g_wT[c * JPAD + jb * 32 + jj];
            float2 d = make_float2(w, w);
            *reinterpret_cast<float2*>(&Ws2[c * 64 + jj * 2]) = d;
        }
        __syncthreads();

        ull a00 = 0, a01 = 0, a10 = 0, a11 = 0;
        ull a20 = 0, a21 = 0, a30 = 0, a31 = 0;

        #pragma unroll 6
        for (int c = 0; c < CV; ++c) {
            ulonglong2 xp  = *reinterpret_cast<const ulonglong2*>(&Xs[c * TTILE + tl]);
            ulonglong2 w01 = *reinterpret_cast<const ulonglong2*>(&Ws2[c * 64 + wy * 8]);
            ulonglong2 w23 = *reinterpret_cast<const ulonglong2*>(&Ws2[c * 64 + wy * 8 + 4]);
            a00 = ffma2(w01.x, xp.x, a00); a01 = ffma2(w01.x, xp.y, a01);
            a10 = ffma2(w01.y, xp.x, a10); a11 = ffma2(w01.y, xp.y, a11);
            a20 = ffma2(w23.x, xp.x, a20); a21 = ffma2(w23.x, xp.y, a21);
            a30 = ffma2(w23.y, xp.x, a30); a31 = ffma2(w23.y, xp.y, a31);
        }

        int j0 = jb * 32 + wy * 4;
        ulonglong2 o;
        if (j0 + 0 < D1V) { o.x = a00; o.y = a01;
            *reinterpret_cast<ulonglong2*>(outp + (size_t)(j0 + 0) * TV) = o; }
        if (j0 + 1 < D1V) { o.x = a10; o.y = a11;
            *reinterpret_cast<ulonglong2*>(outp + (size_t)(j0 + 1) * TV) = o; }
        if (j0 + 2 < D1V) { o.x = a20; o.y = a21;
            *reinterpret_cast<ulonglong2*>(outp + (size_t)(j0 + 2) * TV) = o; }
        if (j0 + 3 < D1V) { o.x = a30; o.y = a31;
            *reinterpret_cast<ulonglong2*>(outp + (size_t)(j0 + 3) * TV) = o; }
    }
}

// ---------------------------------------------------------------------------
extern "C" void kernel_launch(void* const* d_in, const int* in_sizes, int n_in,
                              void* d_out, int out_size) {
    const float* X    = (const float*)d_in[0];
    const float* z_re = (const float*)d_in[1];
    const float* z_im = (const float*)d_in[2];
    const float* loc  = (const float*)d_in[3];
    float* out = (float*)d_out;

    phase_kernel<<<(KL * CV + 255) / 256, 256>>>(loc);
    weight_kernel<<<JPAD, 256>>>(z_re, z_im);
    out_kernel<<<dim3(TV / TTILE, BV), 256>>>(X, out);
}

// round 4
// speedup vs baseline: 8.2133x; 1.0211x over previous
#include <cuda_runtime.h>
#include <math.h>

#define D1V 270
#define KV 32
#define CV 60
#define BV 64
#define TV 4096
#define KL (KV*KV)          // 1024
#define JPAD 288            // 270 padded: 3 passes of 96
#define TTILE 128
#define JB 96               // j per CTA pass
#define JW 12               // j per warp
#define NPASS 3             // JPAD / JB
#define WDUP (JPAD*2)       // 576 floats per c in dup layout

typedef unsigned long long ull;

// Scratch (device globals: no allocation allowed)
__device__ __align__(16) float g_cs[KL*CV];
__device__ __align__(16) float g_sn[KL*CV];
__device__ __align__(16) float g_wT2[CV*WDUP];  // wT2[c][j*2+{0,1}] = {w,w}, 0 for j>=270

// packed fp32x2 FMA (sm_10x): d = a*b + c per 32-bit lane
__device__ __forceinline__ ull ffma2(ull a, ull b, ull c) {
    ull d;
    asm("fma.rn.f32x2 %0, %1, %2, %3;" : "=l"(d) : "l"(a), "l"(b), "l"(c));
    return d;
}

// ---------------------------------------------------------------------------
// Kernel A: trig tables  cs[(k*32+l)*60 + c] = cos(2pi*(k*x[c]+l*y[c]))
// ---------------------------------------------------------------------------
__global__ void phase_kernel(const float* __restrict__ loc) {
    int idx = blockIdx.x * blockDim.x + threadIdx.x;
    if (idx >= KL * CV) return;
    int c  = idx % CV;
    int kl = idx / CV;
    int k = kl >> 5, l = kl & 31;
    float x = loc[c * 2 + 0];
    float y = loc[c * 2 + 1];
    float ph = 6.283185307179586f * ((float)k * x + (float)l * y);
    float s, co;
    sincosf(ph, &s, &co);
    g_cs[idx] = co;
    g_sn[idx] = s;
}

// ---------------------------------------------------------------------------
// Kernel B: a[j,c] = sum_kl z_re*cs + z_im*sn ; softmax over c ;
// write DUPLICATED transposed weights g_wT2[c][j*2+{0,1}].
// 256 threads: c = tid&63 (c<60 active), kl split across 4 groups (tid>>6).
// ---------------------------------------------------------------------------
__global__ void __launch_bounds__(256) weight_kernel(const float* __restrict__ z_re,
                                                     const float* __restrict__ z_im) {
    int j   = blockIdx.x;
    int tid = threadIdx.x;
    int c   = tid & 63;
    int g   = tid >> 6;      // 0..3
    __shared__ float part[256];
    __shared__ float red[64];

    if (j >= D1V) {
        if (tid < CV) {
            g_wT2[tid * WDUP + j * 2 + 0] = 0.f;
            g_wT2[tid * WDUP + j * 2 + 1] = 0.f;
        }
        return;
    }

    float acc = 0.f;
    if (c < CV) {
        const float* zr = z_re + (size_t)j * KL;
        const float* zi = z_im + (size_t)j * KL;
        int kl0 = g * (KL / 4);
        #pragma unroll 8
        for (int kl = kl0; kl < kl0 + KL / 4; ++kl) {
            acc = fmaf(zr[kl], g_cs[kl * CV + c], acc);
            acc = fmaf(zi[kl], g_sn[kl * CV + c], acc);
        }
    }
    part[tid] = acc;
    __syncthreads();

    float tot = 0.f;
    if (tid < 64)
        tot = part[tid] + part[tid + 64] + part[tid + 128] + part[tid + 192];

    if (tid < 64) red[tid] = (tid < CV) ? tot : -3.402823466e38f;
    __syncthreads();
    for (int off = 32; off > 0; off >>= 1) {
        if (tid < off) red[tid] = fmaxf(red[tid], red[tid + off]);
        __syncthreads();
    }
    float m = red[0];
    __syncthreads();

    float e = (tid < CV) ? expf(tot - m) : 0.f;
    if (tid < 64) red[tid] = e;
    __syncthreads();
    for (int off = 32; off > 0; off >>= 1) {
        if (tid < off) red[tid] += red[tid + off];
        __syncthreads();
    }
    float s = red[0];

    if (tid < CV) {
        float w = e / s;
        g_wT2[tid * WDUP + j * 2 + 0] = w;
        g_wT2[tid * WDUP + j * 2 + 1] = w;
    }
}

// ---------------------------------------------------------------------------
// Kernel C: out[b,j,t] = sum_c w[j,c] * X[b,c,t]
// Grid: (T/128, B). 256 threads = 8 warps. Warp wy owns 12 j's; lane owns 4 t's.
// 3 passes of 96 j. X staged once; W slice (duplicated pairs) staged per pass.
// Inner c-iter per warp: 1 LDS.128 (X) + 6 LDS.128 (W broadcast) + 24 FFMA2
//   -> packed-FMA-pipe bound (smem 80 wf < fma 96 cyc per CTA-c).
// ---------------------------------------------------------------------------
__global__ void __launch_bounds__(256) out_kernel(const float* __restrict__ X,
                                                  float* __restrict__ out) {
    extern __shared__ __align__(16) float smem[];
    float* Xs = smem;                 // CV*TTILE   = 7680 floats (30 KB)
    float* Ws = smem + CV * TTILE;    // CV*JB*2    = 11520 floats (45 KB)

    int b   = blockIdx.y;
    int t0  = blockIdx.x * TTILE;
    int tid = threadIdx.x;

    // Stage X[b, :, t0:t0+128] once (vectorized, coalesced)
    const float* Xb = X + (size_t)b * CV * TV + t0;
    for (int idx = tid; idx < CV * (TTILE / 4); idx += 256) {
        int c = idx / (TTILE / 4);
        int q = idx - c * (TTILE / 4);
        reinterpret_cast<float4*>(Xs)[idx] =
            *reinterpret_cast<const float4*>(Xb + (size_t)c * TV + q * 4);
    }

    int lane = tid & 31;
    int wy   = tid >> 5;
    int tl   = lane * 4;
    float* outp = out + (size_t)b * D1V * TV + t0 + tl;

    for (int p = 0; p < NPASS; ++p) {
        __syncthreads();   // prior pass reads done before Ws overwrite (also covers Xs stage)
        // Stage W dup slice: Ws[c*192 + q] = g_wT2[c*576 + p*192 + q], 48 float4 per c
        for (int idx = tid; idx < CV * (JB * 2 / 4); idx += 256) {
            int c = idx / (JB * 2 / 4);
            int q = idx - c * (JB * 2 / 4);
            reinterpret_cast<float4*>(Ws)[c * (JB * 2 / 4) + q] =
                *reinterpret_cast<const float4*>(&g_wT2[c * WDUP + p * (JB * 2) + q * 4]);
        }
        __syncthreads();

        ull acc[JW][2];
        #pragma unroll
        for (int jj = 0; jj < JW; ++jj) { acc[jj][0] = 0; acc[jj][1] = 0; }

        #pragma unroll 2
        for (int c = 0; c < CV; ++c) {
            ulonglong2 xp = *reinterpret_cast<const ulonglong2*>(&Xs[c * TTILE + tl]);
            const ulonglong2* wb =
                reinterpret_cast<const ulonglong2*>(&Ws[c * (JB * 2) + wy * (JW * 2)]);
            #pragma unroll
            for (int q = 0; q < JW / 2; ++q) {
                ulonglong2 wv = wb[q];   // {w(2q),w(2q)} , {w(2q+1),w(2q+1)}
                acc[2*q+0][0] = ffma2(wv.x, xp.x, acc[2*q+0][0]);
                acc[2*q+0][1] = ffma2(wv.x, xp.y, acc[2*q+0][1]);
                acc[2*q+1][0] = ffma2(wv.y, xp.x, acc[2*q+1][0]);
                acc[2*q+1][1] = ffma2(wv.y, xp.y, acc[2*q+1][1]);
            }
        }

        int jbase = p * JB + wy * JW;
        #pragma unroll
        for (int jj = 0; jj < JW; ++jj) {
            int j = jbase + jj;
            if (j < D1V) {
                ulonglong2 o; o.x = acc[jj][0]; o.y = acc[jj][1];
                *reinterpret_cast<ulonglong2*>(outp + (size_t)j * TV) = o;
            }
        }
    }
}

// ---------------------------------------------------------------------------
extern "C" void kernel_launch(void* const* d_in, const int* in_sizes, int n_in,
                              void* d_out, int out_size) {
    const float* X    = (const float*)d_in[0];
    const float* z_re = (const float*)d_in[1];
    const float* z_im = (const float*)d_in[2];
    const float* loc  = (const float*)d_in[3];
    float* out = (float*)d_out;

    const int smem_bytes = (CV * TTILE + CV * JB * 2) * sizeof(float);  // 76800 B
    cudaFuncSetAttribute(out_kernel, cudaFuncAttributeMaxDynamicSharedMemorySize, smem_bytes);

    phase_kernel<<<(KL * CV + 255) / 256, 256>>>(loc);
    weight_kernel<<<JPAD, 256>>>(z_re, z_im);
    out_kernel<<<dim3(TV / TTILE, BV), 256, smem_bytes>>>(X, out);
}

// round 13
// speedup vs baseline: 15.7444x; 1.9169x over previous
#include <cuda_runtime.h>
#include <math.h>
#include <stdint.h>

#define D1V 270
#define KV 32
#define CV 60
#define BV 64
#define TV 4096
#define KL (KV*KV)          // 1024
#define CPAD 64
#define JPAD 288            // 18 x 16
#define NJF 18              // j fragments of 16
#define MT 96               // j per CTA (6 frags)
#define TT 128              // t per CTA
#define XSTR 132            // Xs row stride (pad for conflict-free B gather)

// Scratch (device globals)
__device__ __align__(16) float g_cs[KL*CV];
__device__ __align__(16) float g_sn[KL*CV];
// A pre-packed in m16n8k8 fragment order:
// g_wAf[((jf*8 + kf)*32 + lane)*4 + e],  e = {(+0,+0),(+8j,+0),(+0,+4k),(+8j,+4k)}
__device__ __align__(16) float g_wAf[NJF*8*32*4];

// ---------------------------------------------------------------------------
__device__ __forceinline__ float tf32r(float x) {
    float y;
    asm("cvt.rna.tf32.f32 %0, %1;" : "=f"(y) : "f"(x));
    return y;
}
__device__ __forceinline__ void mma16n8k8(float* d, const uint32_t* a, const uint32_t* b) {
    asm volatile(
        "mma.sync.aligned.m16n8k8.row.col.f32.tf32.tf32.f32 "
        "{%0,%1,%2,%3}, {%4,%5,%6,%7}, {%8,%9}, {%0,%1,%2,%3};"
        : "+f"(d[0]), "+f"(d[1]), "+f"(d[2]), "+f"(d[3])
        : "r"(a[0]), "r"(a[1]), "r"(a[2]), "r"(a[3]), "r"(b[0]), "r"(b[1]));
}

// ---------------------------------------------------------------------------
// Kernel A: trig tables
// ---------------------------------------------------------------------------
__global__ void phase_kernel(const float* __restrict__ loc) {
    int idx = blockIdx.x * blockDim.x + threadIdx.x;
    if (idx >= KL * CV) return;
    int c  = idx % CV;
    int kl = idx / CV;
    int k = kl >> 5, l = kl & 31;
    float x = loc[c * 2 + 0];
    float y = loc[c * 2 + 1];
    float ph = 6.283185307179586f * ((float)k * x + (float)l * y);
    float s, co;
    sincosf(ph, &s, &co);
    g_cs[idx] = co;
    g_sn[idx] = s;
}

// ---------------------------------------------------------------------------
// Kernel B: a[j,c] -> softmax over c -> write tf32-rounded A in FRAGMENT order.
// One block per padded j (288). 256 threads; c = tid&63, kl split 4 ways.
// ---------------------------------------------------------------------------
__global__ void __launch_bounds__(256) weight_kernel(const float* __restrict__ z_re,
                                                     const float* __restrict__ z_im) {
    int j   = blockIdx.x;          // 0..287
    int tid = threadIdx.x;
    int c   = tid & 63;
    int g   = tid >> 6;
    __shared__ float part[256];
    __shared__ float red[64];

    float w = 0.f;
    if (j < D1V) {
        float acc = 0.f;
        if (c < CV) {
            const float* zr = z_re + (size_t)j * KL;
            const float* zi = z_im + (size_t)j * KL;
            int kl0 = g * (KL / 4);
            #pragma unroll 8
            for (int kl = kl0; kl < kl0 + KL / 4; ++kl) {
                acc = fmaf(zr[kl], g_cs[kl * CV + c], acc);
                acc = fmaf(zi[kl], g_sn[kl * CV + c], acc);
            }
        }
        part[tid] = acc;
        __syncthreads();

        float tot = 0.f;
        if (tid < 64)
            tot = part[tid] + part[tid + 64] + part[tid + 128] + part[tid + 192];

        if (tid < 64) red[tid] = (tid < CV) ? tot : -3.402823466e38f;
        __syncthreads();
        for (int off = 32; off > 0; off >>= 1) {
            if (tid < off) red[tid] = fmaxf(red[tid], red[tid + off]);
            __syncthreads();
        }
        float m = red[0];
        __syncthreads();

        float e = (tid < CV) ? expf(tot - m) : 0.f;
        if (tid < 64) red[tid] = e;
        __syncthreads();
        for (int off = 32; off > 0; off >>= 1) {
            if (tid < off) red[tid] += red[tid + off];
            __syncthreads();
        }
        float s = red[0];
        if (tid < CV) w = tf32r(e / s);
    }

    // Scatter into fragment-order layout (one slot per (j, c<64))
    if (tid < CPAD) {
        int jf = j >> 4;
        int r  = j & 15;
        int e1 = r >> 3;
        int lane_hi = r & 7;
        int kf = tid >> 3;
        int kk = tid & 7;
        int e2 = kk >> 2;
        int lane_lo = kk & 3;
        int lane = lane_hi * 4 + lane_lo;
        int e = e1 | (e2 << 1);
        g_wAf[((jf * 8 + kf) * 32 + lane) * 4 + e] = w;
    }
}

// ---------------------------------------------------------------------------
// Kernel C: tf32 mma.sync GEMM. grid (mtile=3, t=32, b=64), 256 threads.
// CTA tile 96j x 128t; 8 warps as 2j x 4t; warp tile 48j x 32t.
// ---------------------------------------------------------------------------
__global__ void __launch_bounds__(256) out_kernel(const float* __restrict__ X,
                                                  float* __restrict__ out) {
    extern __shared__ __align__(16) float smem[];
    float* Asf = smem;                       // 6*8*32*4 = 6144 floats (24 KB)
    float* Xs  = smem + 6 * 8 * 32 * 4;      // 64*132   = 8448 floats (33 KB)

    int tid  = threadIdx.x;
    int lane = tid & 31;
    int wid  = tid >> 5;
    int wj   = wid >> 2;        // 0..1
    int wt   = wid & 3;         // 0..3

    int mtile = blockIdx.x;
    int t0    = blockIdx.y * TT;
    int b     = blockIdx.z;

    // Stage packed A slice (straight float4 copy, 1536 float4)
    {
        const float4* src = (const float4*)(g_wAf + (size_t)mtile * 6 * 8 * 32 * 4);
        float4* dst = (float4*)Asf;
        #pragma unroll
        for (int i = tid; i < 6 * 8 * 32; i += 256) dst[i] = src[i];
    }
    // Stage X[b, c, t0:t0+128] -> Xs[c][t] (stride 132), tf32-rounded, pad c>=60
    {
        const float* Xb = X + (size_t)b * CV * TV + t0;
        #pragma unroll
        for (int idx = tid; idx < CPAD * (TT / 4); idx += 256) {
            int c  = idx >> 5;       // 0..63
            int tq = idx & 31;       // chunks of 4
            float4 v = make_float4(0.f, 0.f, 0.f, 0.f);
            if (c < CV) {
                v = *(const float4*)(Xb + (size_t)c * TV + tq * 4);
                v.x = tf32r(v.x); v.y = tf32r(v.y);
                v.z = tf32r(v.z); v.w = tf32r(v.w);
            }
            float* d = &Xs[c * XSTR + tq * 4];
            d[0] = v.x; d[1] = v.y; d[2] = v.z; d[3] = v.w;
        }
    }
    __syncthreads();

    const uint32_t* Xu = (const uint32_t*)Xs;
    int t0w = wt * 32;

    float acc[3][4][4];
    #pragma unroll
    for (int m = 0; m < 3; ++m)
        #pragma unroll
        for (int n = 0; n < 4; ++n)
            #pragma unroll
            for (int e = 0; e < 4; ++e) acc[m][n][e] = 0.f;

    #pragma unroll
    for (int kf = 0; kf < 8; ++kf) {
        uint32_t af[3][4];
        #pragma unroll
        for (int m = 0; m < 3; ++m) {
            int jfl = wj * 3 + m;
            *(uint4*)af[m] = *(const uint4*)&Asf[((jfl * 8 + kf) * 32 + lane) * 4];
        }
        uint32_t bf[4][2];
        int kb = kf * 8 + (lane & 3);
        int tb = t0w + (lane >> 2);
        #pragma unroll
        for (int n = 0; n < 4; ++n) {
            bf[n][0] = Xu[kb * XSTR + tb + n * 8];
            bf[n][1] = Xu[(kb + 4) * XSTR + tb + n * 8];
        }
        #pragma unroll
        for (int m = 0; m < 3; ++m)
            #pragma unroll
            for (int n = 0; n < 4; ++n)
                mma16n8k8(acc[m][n], af[m], bf[n]);
    }

    // Epilogue: direct stores. c-frag: rows lane>>2 (+8), cols 2*(lane&3) (+1)
    float* outb = out + (size_t)b * D1V * TV + t0;
    #pragma unroll
    for (int m = 0; m < 3; ++m) {
        int j0 = mtile * MT + wj * 48 + m * 16 + (lane >> 2);
        #pragma unroll
        for (int n = 0; n < 4; ++n) {
            int tt = t0w + n * 8 + (lane & 3) * 2;
            if (j0 < D1V)
                *(float2*)(outb + (size_t)j0 * TV + tt) =
                    make_float2(acc[m][n][0], acc[m][n][1]);
            if (j0 + 8 < D1V)
                *(float2*)(outb + (size_t)(j0 + 8) * TV + tt) =
                    make_float2(acc[m][n][2], acc[m][n][3]);
        }
    }
}

// ---------------------------------------------------------------------------
extern "C" void kernel_launch(void* const* d_in, const int* in_sizes, int n_in,
                              void* d_out, int out_size) {
    const float* X    = (const float*)d_in[0];
    const float* z_re = (const float*)d_in[1];
    const float* z_im = (const float*)d_in[2];
    const float* loc  = (const float*)d_in[3];
    float* out = (float*)d_out;

    const int smem_bytes = (6 * 8 * 32 * 4 + CPAD * XSTR) * sizeof(float);  // 58368
    cudaFuncSetAttribute(out_kernel, cudaFuncAttributeMaxDynamicSharedMemorySize, smem_bytes);

    phase_kernel<<<(KL * CV + 255) / 256, 256>>>(loc);
    weight_kernel<<<JPAD, 256>>>(z_re, z_im);
    out_kernel<<<dim3(3, TV / TT, BV), 256, smem_bytes>>>(X, out);
}